// round 12
// baseline (speedup 1.0000x reference)
#include <cuda_runtime.h>
#include <cuda_bf16.h>

// ---------------------------------------------------------------------------
// BiRNN R12: j-paired f32x2 layout. Lane r owns rows (2r,2r+1) + redundant
// row 8; each output has ONE packed accumulator reduced over j-pairs, with a
// horizontal add at the end. State = 4 packed pairs + h8 scalar -> packs per
// step drop from ~14 to ~6. Geometry & tanh identical to R8/R11 (128 blocks
// x 256 threads = 2 warps/SMSP, exact EX2/RCP tanh, SC-prescaled weights,
// x-dot lookahead in the tanh/shfl stall window).
// ---------------------------------------------------------------------------

typedef unsigned long long u64t;

__device__ float g_y[4096 * 18];  // concat(h_fwd, h_bwd) staging

static constexpr float SC = 2.8853900817779268f;  // 2 * log2(e)

__device__ __forceinline__ u64t pk2(float lo, float hi) {
    u64t r;
    asm("mov.b64 %0, {%1, %2};" : "=l"(r) : "f"(lo), "f"(hi));
    return r;
}
__device__ __forceinline__ void upk2(u64t v, float& lo, float& hi) {
    asm("mov.b64 {%0, %1}, %2;" : "=f"(lo), "=f"(hi) : "l"(v));
}
__device__ __forceinline__ u64t f2fma(u64t a, u64t b, u64t c) {
    u64t r;
    asm("fma.rn.f32x2 %0, %1, %2, %3;" : "=l"(r) : "l"(a), "l"(b), "l"(c));
    return r;
}
__device__ __forceinline__ float ex2f_(float x) {
    float r; asm("ex2.approx.f32 %0, %1;" : "=f"(r) : "f"(x)); return r;
}
__device__ __forceinline__ float rcpf_(float x) {
    float r; asm("rcp.approx.f32 %0, %1;" : "=f"(r) : "f"(x)); return r;
}
// s = 2*log2(e)*a ; tanh(a) = 1 - 2/(exp(2a)+1), exact identity, approx units
__device__ __forceinline__ float tanh_sc(float s) {
    float e = ex2f_(s);
    return fmaf(-2.0f, rcpf_(e + 1.0f), 1.0f);
}
__device__ __forceinline__ float getc(const float4& v, int m) {
    return m == 0 ? v.x : (m == 1 ? v.y : (m == 2 ? v.z : v.w));
}

// x-dot lookahead state (by-value copy avoids aliasing between cur and next)
struct XS { u64t a[3]; float s[3]; };

// ---------------------------------------------------------------------------
// RNN1. Local h slot k -> global column (R8 butterfly order):
//   pair0: 2r, 2r+1   pair1: 2(r^1), +1   pair2: 2(r^2), +1
//   pair3: 2((r^2)^1), +1    scalar: 8
// ---------------------------------------------------------------------------
template <bool BACK>
__device__ __forceinline__ void rnn1_body(
    int b, int r, const float* __restrict__ x,
    const float* __restrict__ wih, const float* __restrict__ whh,
    const float* __restrict__ bih, const float* __restrict__ bhh, int T)
{
    const int row0 = 2 * r, row1 = 2 * r + 1;
    int cmap[8];
    cmap[0] = 2 * r;             cmap[1] = 2 * r + 1;
    cmap[2] = 2 * (r ^ 1);       cmap[3] = 2 * (r ^ 1) + 1;
    cmap[4] = 2 * (r ^ 2);       cmap[5] = 2 * (r ^ 2) + 1;
    cmap[6] = 2 * ((r ^ 2) ^ 1); cmap[7] = 2 * ((r ^ 2) ^ 1) + 1;

    const int rows[3] = {row0, row1, 8};

    // ---- weights (pre-scaled by SC), j-paired per output
    u64t WH[3][4]; float W8[3];
    u64t WX[3][2]; float WX4[3];
    u64t BB[3];
#pragma unroll
    for (int o = 0; o < 3; o++) {
        int ro = rows[o];
#pragma unroll
        for (int p = 0; p < 4; p++)
            WH[o][p] = pk2(SC * __ldg(whh + ro * 9 + cmap[2 * p]),
                           SC * __ldg(whh + ro * 9 + cmap[2 * p + 1]));
        W8[o]  = SC * __ldg(whh + ro * 9 + 8);
        WX[o][0] = pk2(SC * __ldg(wih + ro * 5 + 0), SC * __ldg(wih + ro * 5 + 1));
        WX[o][1] = pk2(SC * __ldg(wih + ro * 5 + 2), SC * __ldg(wih + ro * 5 + 3));
        WX4[o] = SC * __ldg(wih + ro * 5 + 4);
        BB[o]  = pk2(SC * (__ldg(bih + ro) + __ldg(bhh + ro)), 0.0f);
    }

    // ---- state: 4 packed pairs + scalar h8
    u64t hp[4];
    float h8 = 0.0f;
#pragma unroll
    for (int p = 0; p < 4; p++) hp[p] = 0ULL;

    const int G = T >> 2;  // 4 steps/group = 20 floats = 5 float4
    const float4* xp = reinterpret_cast<const float4*>(x) + (size_t)b * ((size_t)T * 5 / 4);

    float4 bA[5], bB[5];

    auto LOADG = [&](float4 (&buf)[5], int g) {
        int base = BACK ? 5 * (G - 1 - g) : 5 * g;
#pragma unroll
        for (int k = 0; k < 5; k++) buf[k] = __ldg(xp + base + k);
    };

    // bias + x-dot for one step (h-independent): 2 packs serve all 3 outputs
    auto XDOT = [&](const float4 (&bf)[5], int off) -> XS {
        XS o_;
        float x0 = getc(bf[(off + 0) >> 2], (off + 0) & 3);
        float x1 = getc(bf[(off + 1) >> 2], (off + 1) & 3);
        float x2 = getc(bf[(off + 2) >> 2], (off + 2) & 3);
        float x3 = getc(bf[(off + 3) >> 2], (off + 3) & 3);
        float x4 = getc(bf[(off + 4) >> 2], (off + 4) & 3);
        u64t xp0 = pk2(x0, x1), xp1 = pk2(x2, x3);
#pragma unroll
        for (int o = 0; o < 3; o++) {
            u64t a = f2fma(WX[o][0], xp0, BB[o]);
            o_.a[o] = f2fma(WX[o][1], xp1, a);
            o_.s[o] = WX4[o] * x4;
        }
        return o_;
    };

    // one recurrence step; computes NEXT step's x-dot in the stall window
    auto HSTEP = [&](XS cur, XS& nxt, const float4 (&nbf)[5], int noff) {
        u64t A0 = cur.a[0], A1 = cur.a[1], A2 = cur.a[2];
#pragma unroll
        for (int p = 0; p < 4; p++) {
            A0 = f2fma(WH[0][p], hp[p], A0);
            A1 = f2fma(WH[1][p], hp[p], A1);
            A2 = f2fma(WH[2][p], hp[p], A2);
        }
        // ---- lookahead (h-independent filler) ----
        nxt = XDOT(nbf, noff);
        // ---- horizontal + j=8 term + tanh ----
        float l0, u0, l1, u1, l2, u2;
        upk2(A0, l0, u0); upk2(A1, l1, u1); upk2(A2, l2, u2);
        float s0 = (l0 + u0) + fmaf(W8[0], h8, cur.s[0]);
        float s1 = (l1 + u1) + fmaf(W8[1], h8, cur.s[1]);
        float s2 = (l2 + u2) + fmaf(W8[2], h8, cur.s[2]);
        float o0 = tanh_sc(s0), o1 = tanh_sc(s1);
        h8 = tanh_sc(s2);
        // ---- butterfly broadcast, pack pairs directly ----
        float r0 = __shfl_xor_sync(0xffffffffu, o0, 1);
        float r1 = __shfl_xor_sync(0xffffffffu, o1, 1);
        float q0 = __shfl_xor_sync(0xffffffffu, o0, 2);
        float q1 = __shfl_xor_sync(0xffffffffu, o1, 2);
        float q2 = __shfl_xor_sync(0xffffffffu, r0, 2);
        float q3 = __shfl_xor_sync(0xffffffffu, r1, 2);
        hp[0] = pk2(o0, o1); hp[1] = pk2(r0, r1);
        hp[2] = pk2(q0, q1); hp[3] = pk2(q2, q3);
    };

    const int off0 = (BACK ? 3 : 0) * 5;   // first step's buffer offset

    LOADG(bA, 0);
    XS xc = XDOT(bA, off0);

    for (int g = 0; g < G; g += 2) {
        if (g + 1 < G) LOADG(bB, g + 1);
#pragma unroll
        for (int s = 0; s < 4; s++) {
            if (s < 3) HSTEP(xc, xc, bA, (BACK ? (2 - s) : (s + 1)) * 5);
            else       HSTEP(xc, xc, bB, off0);
        }
        if (g + 2 < G) LOADG(bA, g + 2);
#pragma unroll
        for (int s = 0; s < 4; s++) {
            if (s < 3) HSTEP(xc, xc, bB, (BACK ? (2 - s) : (s + 1)) * 5);
            else       HSTEP(xc, xc, bA, off0);
        }
    }

    // writeback: own rows + row 8 (identical on all lanes -> benign dup store)
    float h0, h1;
    upk2(hp[0], h0, h1);
    float* dst = g_y + (size_t)b * 18 + (BACK ? 9 : 0);
    dst[row0] = h0; dst[row1] = h1; dst[8] = h8;
}

__global__ void __launch_bounds__(256, 1) rnn1_kernel(
    const float* __restrict__ x,
    const float* __restrict__ wih_f, const float* __restrict__ whh_f,
    const float* __restrict__ bih_f, const float* __restrict__ bhh_f,
    const float* __restrict__ wih_b, const float* __restrict__ whh_b,
    const float* __restrict__ bih_b, const float* __restrict__ bhh_b,
    int T, int B)
{
    int gtid = blockIdx.x * blockDim.x + threadIdx.x;
    int r     = gtid & 3;
    int chain = gtid >> 2;         // [0, 2B); first B fwd, second B bwd
    if (chain < B) {
        rnn1_body<false>(chain, r, x, wih_f, whh_f, bih_f, bhh_f, T);
    } else {
        rnn1_body<true>(chain - B, r, x, wih_b, whh_b, bih_b, bhh_b, T);
    }
}

// ---------------------------------------------------------------------------
// RNN2 + projection: warp per batch, smem h-broadcast, split accumulators.
// (R8 version, best measured ~21us)
// ---------------------------------------------------------------------------
#define ROWF 36  // padded row stride (floats): 16B-aligned, conflict-free

__global__ void __launch_bounds__(128) rnn2_kernel(
    const float* __restrict__ wih2, const float* __restrict__ whh2,
    const float* __restrict__ bih2, const float* __restrict__ bhh2,
    const float* __restrict__ wout, const float* __restrict__ bout,
    float* __restrict__ out, int B)
{
    __shared__ __align__(16) float hbuf[4][25 * ROWF];
    __shared__ float wsm[96];

    int tid = threadIdx.x;
    int wid = tid >> 5;
    int lane = tid & 31;
    int b = blockIdx.x * 4 + wid;

    if (tid < 96) wsm[tid] = __ldg(wout + tid);
    __syncthreads();
    if (b >= B) return;

    float WHR[32];
    {
        const float4* wr = reinterpret_cast<const float4*>(whh2 + lane * 32);
#pragma unroll
        for (int q = 0; q < 8; q++) {
            float4 v = __ldg(wr + q);
            WHR[4 * q + 0] = SC * v.x; WHR[4 * q + 1] = SC * v.y;
            WHR[4 * q + 2] = SC * v.z; WHR[4 * q + 3] = SC * v.w;
        }
    }
    float bi = SC * (__ldg(bih2 + lane) + __ldg(bhh2 + lane));

    // step 0: input y from g_y, two partial chains
    const float* yb = g_y + (size_t)b * 18;
    float ac0 = bi, ac1 = 0.0f;
#pragma unroll
    for (int j = 0; j < 9; j++)
        ac0 = fmaf(SC * __ldg(wih2 + lane * 18 + j), __ldg(yb + j), ac0);
#pragma unroll
    for (int j = 9; j < 18; j++)
        ac1 = fmaf(SC * __ldg(wih2 + lane * 18 + j), __ldg(yb + j), ac1);
    float h = tanh_sc(ac0 + ac1);

    float* hr = hbuf[wid];
    hr[lane] = h;
    __syncwarp();

#pragma unroll 1
    for (int t = 1; t < 25; t++) {
        const float4* rp = reinterpret_cast<const float4*>(hr + (t - 1) * ROWF);
        float p0 = bi, p1 = 0.0f, p2 = 0.0f, p3 = 0.0f;
#pragma unroll
        for (int q = 0; q < 8; q++) {
            float4 v = rp[q];
            float* pp = (q < 2) ? &p0 : ((q < 4) ? &p1 : ((q < 6) ? &p2 : &p3));
            *pp = fmaf(WHR[4 * q + 0], v.x, *pp);
            *pp = fmaf(WHR[4 * q + 1], v.y, *pp);
            *pp = fmaf(WHR[4 * q + 2], v.z, *pp);
            *pp = fmaf(WHR[4 * q + 3], v.w, *pp);
        }
        h = tanh_sc((p0 + p1) + (p2 + p3));
        hr[t * ROWF + lane] = h;
        __syncwarp();
    }

    // epilogue: 75 outputs -> lanes (idx = lane, lane+32, lane+64)
    float bo0 = __ldg(bout + 0), bo1 = __ldg(bout + 1), bo2 = __ldg(bout + 2);
    float* ob = out + (size_t)b * 75;
#pragma unroll
    for (int k = 0; k < 3; k++) {
        int idx = lane + 32 * k;
        if (idx < 75) {
            int t = idx / 3;
            int o = idx - 3 * t;
            const float4* rp = reinterpret_cast<const float4*>(hr + t * ROWF);
            float p0 = (o == 0) ? bo0 : ((o == 1) ? bo1 : bo2);
            float p1 = 0.0f, p2 = 0.0f, p3 = 0.0f;
#pragma unroll
            for (int q = 0; q < 8; q++) {
                float4 v = rp[q];
                float* pp = (q < 2) ? &p0 : ((q < 4) ? &p1 : ((q < 6) ? &p2 : &p3));
                *pp = fmaf(wsm[o * 32 + 4 * q + 0], v.x, *pp);
                *pp = fmaf(wsm[o * 32 + 4 * q + 1], v.y, *pp);
                *pp = fmaf(wsm[o * 32 + 4 * q + 2], v.z, *pp);
                *pp = fmaf(wsm[o * 32 + 4 * q + 3], v.w, *pp);
            }
            ob[idx] = (p0 + p1) + (p2 + p3);
        }
    }
}

// ---------------------------------------------------------------------------
extern "C" void kernel_launch(void* const* d_in, const int* in_sizes, int n_in,
                              void* d_out, int out_size)
{
    const float* x      = (const float*)d_in[0];
    const float* wih_f  = (const float*)d_in[1];
    const float* whh_f  = (const float*)d_in[2];
    const float* bih_f  = (const float*)d_in[3];
    const float* bhh_f  = (const float*)d_in[4];
    const float* wih_b  = (const float*)d_in[5];
    const float* whh_b  = (const float*)d_in[6];
    const float* bih_b  = (const float*)d_in[7];
    const float* bhh_b  = (const float*)d_in[8];
    const float* wih2   = (const float*)d_in[9];
    const float* whh2   = (const float*)d_in[10];
    const float* bih2   = (const float*)d_in[11];
    const float* bhh2   = (const float*)d_in[12];
    const float* wout   = (const float*)d_in[13];
    const float* bout   = (const float*)d_in[14];
    float* out = (float*)d_out;

    int B = out_size / 75;                 // 4096
    int T = in_sizes[0] / (B * 5);         // 2048

    // 4 lanes/chain, 1 chain/thread: 2B chains * 4 = 8*B threads.
    // Blocks of 256 -> 128 blocks -> 1 block/SM -> 2 warps per SMSP.
    int blocks1 = (8 * B) / 256;           // 128
    rnn1_kernel<<<blocks1, 256>>>(x, wih_f, whh_f, bih_f, bhh_f,
                                  wih_b, whh_b, bih_b, bhh_b, T, B);

    rnn2_kernel<<<B / 4, 128>>>(wih2, whh2, bih2, bhh2, wout, bout, out, B);
}